// round 10
// baseline (speedup 1.0000x reference)
#include <cuda_runtime.h>
#include <cuda_fp16.h>
#include <math.h>
#include <stdint.h>

#define T_TOK 8192
#define D_DIM 1024
#define H_DIM 4096
#define E_NUM 8
#define OUT_ELEMS (T_TOK * D_DIM)

// ---------------- scratch ----------------
__device__ __half g_x16[(size_t)T_TOK * D_DIM];            // 16 MiB
__device__ __half g_w1h[(size_t)E_NUM * D_DIM * H_DIM];    // 64 MiB
__device__ __half g_w2h[(size_t)E_NUM * H_DIM * D_DIM];    // 64 MiB
__device__ __half g_mid[(size_t)2 * T_TOK * H_DIM];        // 128 MiB
__device__ float  g_out2[(size_t)2 * T_TOK * D_DIM];       // 64 MiB
__device__ int   g_cnt[E_NUM];
__device__ int   g_tok[E_NUM * T_TOK];
__device__ int   g_slot[E_NUM * T_TOK];
__device__ float g_wt[E_NUM * T_TOK];

__device__ __forceinline__ uint32_t smem_u32(const void* p) {
    uint32_t a;
    asm("{ .reg .u64 t; cvta.to.shared.u64 t, %1; cvt.u32.u64 %0, t; }" : "=r"(a) : "l"(p));
    return a;
}
__device__ __forceinline__ void cp16(uint32_t dst, const void* src) {
    asm volatile("cp.async.cg.shared.global [%0], [%1], 16;" :: "r"(dst), "l"(src) : "memory");
}
__device__ __forceinline__ void cp_commit() {
    asm volatile("cp.async.commit_group;" ::: "memory");
}
template<int N>
__device__ __forceinline__ void cp_wait() {
    asm volatile("cp.async.wait_group %0;" :: "n"(N) : "memory");
}
__device__ __forceinline__ void ldsm_x4(uint32_t* r, uint32_t addr) {
    asm volatile("ldmatrix.sync.aligned.m8n8.x4.shared.b16 {%0,%1,%2,%3}, [%4];"
                 : "=r"(r[0]), "=r"(r[1]), "=r"(r[2]), "=r"(r[3]) : "r"(addr));
}
__device__ __forceinline__ void ldsm_x4_t(uint32_t* r, uint32_t addr) {
    asm volatile("ldmatrix.sync.aligned.m8n8.x4.trans.shared.b16 {%0,%1,%2,%3}, [%4];"
                 : "=r"(r[0]), "=r"(r[1]), "=r"(r[2]), "=r"(r[3]) : "r"(addr));
}
__device__ __forceinline__ void mma16816(float* c, const uint32_t* a, const uint32_t* b) {
    asm volatile(
        "mma.sync.aligned.m16n8k16.row.col.f32.f16.f16.f32 "
        "{%0,%1,%2,%3}, {%4,%5,%6,%7}, {%8,%9}, {%0,%1,%2,%3};"
        : "+f"(c[0]), "+f"(c[1]), "+f"(c[2]), "+f"(c[3])
        : "r"(a[0]), "r"(a[1]), "r"(a[2]), "r"(a[3]), "r"(b[0]), "r"(b[1]));
}

// ---------------- small kernels ----------------
__global__ void zero_cnt_kernel() {
    if (threadIdx.x < E_NUM) g_cnt[threadIdx.x] = 0;
}

__global__ __launch_bounds__(256) void convert_kernel(
    const float4* __restrict__ src, uint4* __restrict__ dst, int n8) {
    int i = blockIdx.x * blockDim.x + threadIdx.x;
    if (i >= n8) return;
    float4 v0 = src[2 * i], v1 = src[2 * i + 1];
    __half2 h0 = __floats2half2_rn(v0.x, v0.y);
    __half2 h1 = __floats2half2_rn(v0.z, v0.w);
    __half2 h2 = __floats2half2_rn(v1.x, v1.y);
    __half2 h3 = __floats2half2_rn(v1.z, v1.w);
    dst[i] = make_uint4(*(uint32_t*)&h0, *(uint32_t*)&h1,
                        *(uint32_t*)&h2, *(uint32_t*)&h3);
}

__global__ __launch_bounds__(256) void combine_kernel(float4* __restrict__ out) {
    int i = blockIdx.x * blockDim.x + threadIdx.x;
    if (i >= OUT_ELEMS / 4) return;
    int t = i / (D_DIM / 4);
    int r = i % (D_DIM / 4);
    const float4* a = (const float4*)g_out2 + (size_t)(2 * t) * (D_DIM / 4) + r;
    const float4* b = (const float4*)g_out2 + (size_t)(2 * t + 1) * (D_DIM / 4) + r;
    float4 va = *a, vb = *b;
    out[i] = make_float4(va.x + vb.x, va.y + vb.y, va.z + vb.z, va.w + vb.w);
}

// Router: one warp per token; also emits fp16 copy of x (fused convert).
__global__ __launch_bounds__(256) void router_kernel(
    const float* __restrict__ x, const float* __restrict__ gw,
    const float* __restrict__ gb, float* __restrict__ logits_out) {
    int warp = (blockIdx.x * blockDim.x + threadIdx.x) >> 5;
    int lane = threadIdx.x & 31;
    if (warp >= T_TOK) return;
    int t = warp;

    float acc[E_NUM];
#pragma unroll
    for (int e = 0; e < E_NUM; e++) acc[e] = 0.f;
    const float4* xr4 = (const float4*)(x + (size_t)t * D_DIM);
    uint2* xo = (uint2*)(g_x16 + (size_t)t * D_DIM);
#pragma unroll 1
    for (int d4 = lane; d4 < D_DIM / 4; d4 += 32) {
        float4 xv = xr4[d4];
        __half2 h0 = __floats2half2_rn(xv.x, xv.y);
        __half2 h1 = __floats2half2_rn(xv.z, xv.w);
        xo[d4] = make_uint2(*(uint32_t*)&h0, *(uint32_t*)&h1);
        const float* gwp = gw + (size_t)(d4 * 4) * E_NUM;
#pragma unroll
        for (int j = 0; j < 4; j++) {
            float xs = (j == 0) ? xv.x : (j == 1) ? xv.y : (j == 2) ? xv.z : xv.w;
            const float4* g4 = (const float4*)(gwp + (size_t)j * E_NUM);
            float4 a = g4[0], b = g4[1];
            acc[0] += xs * a.x; acc[1] += xs * a.y; acc[2] += xs * a.z; acc[3] += xs * a.w;
            acc[4] += xs * b.x; acc[5] += xs * b.y; acc[6] += xs * b.z; acc[7] += xs * b.w;
        }
    }
#pragma unroll
    for (int e = 0; e < E_NUM; e++)
#pragma unroll
        for (int off = 16; off; off >>= 1)
            acc[e] += __shfl_xor_sync(0xffffffffu, acc[e], off);

    if (lane == 0) {
        float l[E_NUM];
#pragma unroll
        for (int e = 0; e < E_NUM; e++) {
            l[e] = acc[e] + gb[e];
            logits_out[t * E_NUM + e] = l[e];
        }
        float m = l[0];
#pragma unroll
        for (int e = 1; e < E_NUM; e++) m = fmaxf(m, l[e]);
        float p[E_NUM], s = 0.f;
#pragma unroll
        for (int e = 0; e < E_NUM; e++) { p[e] = expf(l[e] - m); s += p[e]; }
#pragma unroll
        for (int e = 0; e < E_NUM; e++) p[e] = p[e] / s;
        int e0 = 0;
#pragma unroll
        for (int e = 1; e < E_NUM; e++) if (p[e] > p[e0]) e0 = e;
        int e1 = (e0 == 0) ? 1 : 0;
#pragma unroll
        for (int e = 0; e < E_NUM; e++)
            if (e != e0 && p[e] > p[e1]) e1 = e;
        float denom = p[e0] + p[e1];

        int pos0 = atomicAdd(&g_cnt[e0], 1);
        g_tok[e0 * T_TOK + pos0]  = t;
        g_slot[e0 * T_TOK + pos0] = 2 * t;
        g_wt[e0 * T_TOK + pos0]   = p[e0] / denom;
        int pos1 = atomicAdd(&g_cnt[e1], 1);
        g_tok[e1 * T_TOK + pos1]  = t;
        g_slot[e1 * T_TOK + pos1] = 2 * t + 1;
        g_wt[e1 * T_TOK + pos1]   = p[e1] / denom;
    }
}

// ------- grouped GEMM: 128x128 tile, warp 64x32, cp.async 4-stage, 2 CTA/SM --
// (identical to the proven 1102us R7 configuration)
#define ASTR 40      // halfs per A smem row (32 + 8 pad) = 80B
#define BSTR 136     // halfs per B smem row (128 + 8 pad) = 272B
#define A_STAGE_B (128 * ASTR * 2)          // 10240
#define B_STAGE_B (32 * BSTR * 2)           // 8704
#define STAGE_B   (A_STAGE_B + B_STAGE_B)   // 18944
#define STAGES    4
#define SM_DYN    (STAGES * STAGE_B)        // 75776

template<int KTOT, int NTOT, bool FFN1>
__global__ __launch_bounds__(256, 2) void moe_gemm_kernel(
    const __half* __restrict__ Ain, const __half* __restrict__ W16,
    const float* __restrict__ Bias)
{
    const int NC = KTOT / 32;
    int e = blockIdx.z;
    int cnt = g_cnt[e];
    int rowbase = blockIdx.x * 128;
    if (rowbase >= cnt) return;
    int nbase = blockIdx.y * 128;
    int tid = threadIdx.x;
    int lane = tid & 31;
    int warp = tid >> 5;
    int wm = warp >> 2, wn = warp & 3;    // 2 x 4 warps, warp tile 64x32

    extern __shared__ char smdyn[];
    __shared__ int   dst_s[128];
    __shared__ float wt_s[128];
    __shared__ float bias_s[128];
    __shared__ int   src_s[128];

    if (tid < 128) {
        int r = rowbase + tid;
        int src = 0, dst = -1; float w = 0.f;
        if (r < cnt) {
            if (FFN1) { src = g_tok[e * T_TOK + r];  dst = g_slot[e * T_TOK + r]; }
            else      { src = g_slot[e * T_TOK + r]; dst = g_slot[e * T_TOK + r];
                        w = g_wt[e * T_TOK + r]; }
        }
        src_s[tid] = src; dst_s[tid] = dst; wt_s[tid] = w;
        bias_s[tid] = Bias[(size_t)e * NTOT + nbase + tid];
    }
    __syncthreads();

    uint32_t smb = smem_u32(smdyn);

    int arow = tid >> 1;
    int acol = (tid & 1) * 16;
    const __half* aP = Ain + (size_t)src_s[arow] * KTOT + acol;
    uint32_t a_dst0 = (uint32_t)(arow * ASTR + acol) * 2;
    int brow = tid >> 3;
    int bcol = (tid & 7) * 16;
    const __half* bP = W16 + (size_t)e * KTOT * NTOT + (size_t)brow * NTOT + nbase + bcol;
    uint32_t b_dst0 = (uint32_t)(A_STAGE_B) + (uint32_t)(brow * BSTR + bcol) * 2;

    int lr = lane & 15, lc = lane >> 4;
    uint32_t a_ld0 = (uint32_t)((wm * 64 + lr) * ASTR + lc * 8) * 2;
    uint32_t b_ld0 = (uint32_t)(A_STAGE_B) + (uint32_t)(lr * BSTR + wn * 32 + lc * 8) * 2;

    float acc[4][4][4];
#pragma unroll
    for (int i = 0; i < 4; i++)
#pragma unroll
        for (int j = 0; j < 4; j++)
#pragma unroll
            for (int k = 0; k < 4; k++) acc[i][j][k] = 0.f;

#pragma unroll 1
    for (int s = 0; s < STAGES - 1; s++) {
        uint32_t sb = smb + (uint32_t)s * STAGE_B;
        int k0 = s * 32;
        const __half* ap = aP + k0;
        cp16(sb + a_dst0,      ap);
        cp16(sb + a_dst0 + 16, ap + 8);
        const __half* bp = bP + (size_t)k0 * NTOT;
        cp16(sb + b_dst0,      bp);
        cp16(sb + b_dst0 + 16, bp + 8);
        cp_commit();
    }

#pragma unroll 1
    for (int c = 0; c < NC; c++) {
        cp_wait<STAGES - 2>();
        __syncthreads();
        if (c + STAGES - 1 < NC) {
            int cs = c + STAGES - 1;
            uint32_t sbw = smb + (uint32_t)(cs % STAGES) * STAGE_B;
            int k0 = cs * 32;
            const __half* ap = aP + k0;
            cp16(sbw + a_dst0,      ap);
            cp16(sbw + a_dst0 + 16, ap + 8);
            const __half* bp = bP + (size_t)k0 * NTOT;
            cp16(sbw + b_dst0,      bp);
            cp16(sbw + b_dst0 + 16, bp + 8);
        }
        cp_commit();
        uint32_t sb = smb + (uint32_t)(c % STAGES) * STAGE_B;
#pragma unroll
        for (int ks = 0; ks < 2; ks++) {
            uint32_t afr[4][4], bfr[2][4];
#pragma unroll
            for (int mf = 0; mf < 4; mf++)
                ldsm_x4(afr[mf], sb + a_ld0 + (uint32_t)(mf * 16 * ASTR + ks * 16) * 2);
#pragma unroll
            for (int np = 0; np < 2; np++)
                ldsm_x4_t(bfr[np], sb + b_ld0 + (uint32_t)(ks * 16 * BSTR + np * 16) * 2);
#pragma unroll
            for (int mf = 0; mf < 4; mf++)
#pragma unroll
                for (int nf = 0; nf < 4; nf++)
                    mma16816(acc[mf][nf], afr[mf], &bfr[nf >> 1][(nf & 1) * 2]);
        }
    }

    // ---- epilogue ----
    int crow = lane >> 2;
    int ccol = (lane & 3) * 2;
#pragma unroll
    for (int mf = 0; mf < 4; mf++) {
#pragma unroll
        for (int half_ = 0; half_ < 2; half_++) {
            int mloc = wm * 64 + mf * 16 + crow + half_ * 8;
            int dst = dst_s[mloc];
            if (dst < 0) continue;
            float wv = wt_s[mloc];
#pragma unroll
            for (int nf = 0; nf < 4; nf++) {
                int nloc = wn * 32 + nf * 8 + ccol;
                float v0 = acc[mf][nf][half_ * 2 + 0] + bias_s[nloc];
                float v1 = acc[mf][nf][half_ * 2 + 1] + bias_s[nloc + 1];
                if (FFN1) {
                    v0 = 0.5f * v0 * (1.0f + erff(v0 * 0.70710678118654752f));
                    v1 = 0.5f * v1 * (1.0f + erff(v1 * 0.70710678118654752f));
                    __half2 h = __floats2half2_rn(v0, v1);
                    *(__half2*)(g_mid + (size_t)dst * NTOT + nbase + nloc) = h;
                } else {
                    float2 o = make_float2(wv * v0, wv * v1);
                    *(float2*)(g_out2 + (size_t)dst * NTOT + nbase + nloc) = o;
                }
            }
        }
    }
}

// ---------------------------------------------------------------------------
extern "C" void kernel_launch(void* const* d_in, const int* in_sizes, int n_in,
                              void* d_out, int out_size) {
    const float* x      = (const float*)d_in[0];
    const float* gate_w = (const float*)d_in[1];
    const float* gate_b = (const float*)d_in[2];
    const float* w1     = (const float*)d_in[3];
    const float* b1     = (const float*)d_in[4];
    const float* w2     = (const float*)d_in[5];
    const float* b2     = (const float*)d_in[6];
    float* out    = (float*)d_out;
    float* logits = (float*)d_out + OUT_ELEMS;
    (void)in_sizes; (void)n_in; (void)out_size;

    __half *px, *pw1, *pw2, *pmid;
    cudaGetSymbolAddress((void**)&px,   g_x16);
    cudaGetSymbolAddress((void**)&pw1,  g_w1h);
    cudaGetSymbolAddress((void**)&pw2,  g_w2h);
    cudaGetSymbolAddress((void**)&pmid, g_mid);

    cudaFuncSetAttribute(moe_gemm_kernel<D_DIM, H_DIM, true>,
                         cudaFuncAttributeMaxDynamicSharedMemorySize, SM_DYN);
    cudaFuncSetAttribute(moe_gemm_kernel<H_DIM, D_DIM, false>,
                         cudaFuncAttributeMaxDynamicSharedMemorySize, SM_DYN);

    zero_cnt_kernel<<<1, 32>>>();
    router_kernel<<<(T_TOK * 32) / 256, 256>>>(x, gate_w, gate_b, logits);

    int nw8 = E_NUM * D_DIM * H_DIM / 8;
    convert_kernel<<<(nw8 + 255) / 256, 256>>>((const float4*)w1, (uint4*)pw1, nw8);
    convert_kernel<<<(nw8 + 255) / 256, 256>>>((const float4*)w2, (uint4*)pw2, nw8);

    dim3 g1(T_TOK / 128, H_DIM / 128, E_NUM);   // (64, 32, 8)
    moe_gemm_kernel<D_DIM, H_DIM, true><<<g1, 256, SM_DYN>>>(px, pw1, b1);

    dim3 g2(T_TOK / 128, D_DIM / 128, E_NUM);   // (64, 8, 8)
    moe_gemm_kernel<H_DIM, D_DIM, false><<<g2, 256, SM_DYN>>>(pmid, pw2, b2);

    combine_kernel<<<(OUT_ELEMS / 4 + 255) / 256, 256>>>((float4*)out);
}

// round 12
// speedup vs baseline: 1.0309x; 1.0309x over previous
#include <cuda_runtime.h>
#include <cuda_fp16.h>
#include <math.h>
#include <stdint.h>

#define T_TOK 8192
#define D_DIM 1024
#define H_DIM 4096
#define E_NUM 8
#define OUT_ELEMS (T_TOK * D_DIM)

// ---------------- scratch ----------------
__device__ __half g_x16[(size_t)T_TOK * D_DIM];            // 16 MiB
__device__ __half g_w1h[(size_t)E_NUM * D_DIM * H_DIM];    // 64 MiB
__device__ __half g_w2h[(size_t)E_NUM * H_DIM * D_DIM];    // 64 MiB
__device__ __half g_mid[(size_t)2 * T_TOK * H_DIM];        // 128 MiB
__device__ float  g_out2[(size_t)2 * T_TOK * D_DIM];       // 64 MiB
__device__ int   g_cnt[E_NUM];
__device__ int   g_tok[E_NUM * T_TOK];
__device__ int   g_slot[E_NUM * T_TOK];
__device__ float g_wt[E_NUM * T_TOK];

__device__ __forceinline__ uint32_t smem_u32(const void* p) {
    uint32_t a;
    asm("{ .reg .u64 t; cvta.to.shared.u64 t, %1; cvt.u32.u64 %0, t; }" : "=r"(a) : "l"(p));
    return a;
}
__device__ __forceinline__ void cp16(uint32_t dst, const void* src) {
    asm volatile("cp.async.cg.shared.global [%0], [%1], 16;" :: "r"(dst), "l"(src) : "memory");
}
__device__ __forceinline__ void cp_commit() {
    asm volatile("cp.async.commit_group;" ::: "memory");
}
template<int N>
__device__ __forceinline__ void cp_wait() {
    asm volatile("cp.async.wait_group %0;" :: "n"(N) : "memory");
}
__device__ __forceinline__ void ldsm_x4(uint32_t* r, uint32_t addr) {
    asm volatile("ldmatrix.sync.aligned.m8n8.x4.shared.b16 {%0,%1,%2,%3}, [%4];"
                 : "=r"(r[0]), "=r"(r[1]), "=r"(r[2]), "=r"(r[3]) : "r"(addr));
}
__device__ __forceinline__ void ldsm_x4_t(uint32_t* r, uint32_t addr) {
    asm volatile("ldmatrix.sync.aligned.m8n8.x4.trans.shared.b16 {%0,%1,%2,%3}, [%4];"
                 : "=r"(r[0]), "=r"(r[1]), "=r"(r[2]), "=r"(r[3]) : "r"(addr));
}
__device__ __forceinline__ void mma16816(float* c, const uint32_t* a, const uint32_t* b) {
    asm volatile(
        "mma.sync.aligned.m16n8k16.row.col.f32.f16.f16.f32 "
        "{%0,%1,%2,%3}, {%4,%5,%6,%7}, {%8,%9}, {%0,%1,%2,%3};"
        : "+f"(c[0]), "+f"(c[1]), "+f"(c[2]), "+f"(c[3])
        : "r"(a[0]), "r"(a[1]), "r"(a[2]), "r"(a[3]), "r"(b[0]), "r"(b[1]));
}

// ---------------- small kernels ----------------
__global__ void zero_cnt_kernel() {
    if (threadIdx.x < E_NUM) g_cnt[threadIdx.x] = 0;
}

__global__ __launch_bounds__(256) void convert_kernel(
    const float4* __restrict__ src, uint4* __restrict__ dst, int n8) {
    int i = blockIdx.x * blockDim.x + threadIdx.x;
    if (i >= n8) return;
    float4 v0 = src[2 * i], v1 = src[2 * i + 1];
    __half2 h0 = __floats2half2_rn(v0.x, v0.y);
    __half2 h1 = __floats2half2_rn(v0.z, v0.w);
    __half2 h2 = __floats2half2_rn(v1.x, v1.y);
    __half2 h3 = __floats2half2_rn(v1.z, v1.w);
    dst[i] = make_uint4(*(uint32_t*)&h0, *(uint32_t*)&h1,
                        *(uint32_t*)&h2, *(uint32_t*)&h3);
}

__global__ __launch_bounds__(256) void combine_kernel(float4* __restrict__ out) {
    int i = blockIdx.x * blockDim.x + threadIdx.x;
    if (i >= OUT_ELEMS / 4) return;
    int t = i / (D_DIM / 4);
    int r = i % (D_DIM / 4);
    const float4* a = (const float4*)g_out2 + (size_t)(2 * t) * (D_DIM / 4) + r;
    const float4* b = (const float4*)g_out2 + (size_t)(2 * t + 1) * (D_DIM / 4) + r;
    float4 va = *a, vb = *b;
    out[i] = make_float4(va.x + vb.x, va.y + vb.y, va.z + vb.z, va.w + vb.w);
}

// Router: one warp per token (R7 structure, compiler-unrolled loop) +
// a single coalesced fp16 store per element (fused x convert).
__global__ __launch_bounds__(256) void router_kernel(
    const float* __restrict__ x, const float* __restrict__ gw,
    const float* __restrict__ gb, float* __restrict__ logits_out) {
    int warp = (blockIdx.x * blockDim.x + threadIdx.x) >> 5;
    int lane = threadIdx.x & 31;
    if (warp >= T_TOK) return;
    int t = warp;

    float acc[E_NUM];
#pragma unroll
    for (int e = 0; e < E_NUM; e++) acc[e] = 0.f;
    const float* xr = x + (size_t)t * D_DIM;
    __half* xo = g_x16 + (size_t)t * D_DIM;
    for (int d = lane; d < D_DIM; d += 32) {
        float xv = xr[d];
        xo[d] = __float2half_rn(xv);            // fused convert (64B/warp/iter)
        const float4* g4 = (const float4*)(gw + (size_t)d * E_NUM);
        float4 a = g4[0], b = g4[1];
        acc[0] += xv * a.x; acc[1] += xv * a.y; acc[2] += xv * a.z; acc[3] += xv * a.w;
        acc[4] += xv * b.x; acc[5] += xv * b.y; acc[6] += xv * b.z; acc[7] += xv * b.w;
    }
#pragma unroll
    for (int e = 0; e < E_NUM; e++)
#pragma unroll
        for (int off = 16; off; off >>= 1)
            acc[e] += __shfl_xor_sync(0xffffffffu, acc[e], off);

    if (lane == 0) {
        float l[E_NUM];
#pragma unroll
        for (int e = 0; e < E_NUM; e++) {
            l[e] = acc[e] + gb[e];
            logits_out[t * E_NUM + e] = l[e];
        }
        float m = l[0];
#pragma unroll
        for (int e = 1; e < E_NUM; e++) m = fmaxf(m, l[e]);
        float p[E_NUM], s = 0.f;
#pragma unroll
        for (int e = 0; e < E_NUM; e++) { p[e] = expf(l[e] - m); s += p[e]; }
#pragma unroll
        for (int e = 0; e < E_NUM; e++) p[e] = p[e] / s;
        int e0 = 0;
#pragma unroll
        for (int e = 1; e < E_NUM; e++) if (p[e] > p[e0]) e0 = e;
        int e1 = (e0 == 0) ? 1 : 0;
#pragma unroll
        for (int e = 0; e < E_NUM; e++)
            if (e != e0 && p[e] > p[e1]) e1 = e;
        float denom = p[e0] + p[e1];

        int pos0 = atomicAdd(&g_cnt[e0], 1);
        g_tok[e0 * T_TOK + pos0]  = t;
        g_slot[e0 * T_TOK + pos0] = 2 * t;
        g_wt[e0 * T_TOK + pos0]   = p[e0] / denom;
        int pos1 = atomicAdd(&g_cnt[e1], 1);
        g_tok[e1 * T_TOK + pos1]  = t;
        g_slot[e1 * T_TOK + pos1] = 2 * t + 1;
        g_wt[e1 * T_TOK + pos1]   = p[e1] / denom;
    }
}

// ------- grouped GEMM: 128x128 tile, warp 64x32, cp.async 4-stage, 2 CTA/SM --
// (byte-identical to the proven 1102us R7 configuration)
#define ASTR 40      // halfs per A smem row (32 + 8 pad) = 80B
#define BSTR 136     // halfs per B smem row (128 + 8 pad) = 272B
#define A_STAGE_B (128 * ASTR * 2)          // 10240
#define B_STAGE_B (32 * BSTR * 2)           // 8704
#define STAGE_B   (A_STAGE_B + B_STAGE_B)   // 18944
#define STAGES    4
#define SM_DYN    (STAGES * STAGE_B)        // 75776

template<int KTOT, int NTOT, bool FFN1>
__global__ __launch_bounds__(256, 2) void moe_gemm_kernel(
    const __half* __restrict__ Ain, const __half* __restrict__ W16,
    const float* __restrict__ Bias)
{
    const int NC = KTOT / 32;
    int e = blockIdx.z;
    int cnt = g_cnt[e];
    int rowbase = blockIdx.x * 128;
    if (rowbase >= cnt) return;
    int nbase = blockIdx.y * 128;
    int tid = threadIdx.x;
    int lane = tid & 31;
    int warp = tid >> 5;
    int wm = warp >> 2, wn = warp & 3;    // 2 x 4 warps, warp tile 64x32

    extern __shared__ char smdyn[];
    __shared__ int   dst_s[128];
    __shared__ float wt_s[128];
    __shared__ float bias_s[128];
    __shared__ int   src_s[128];

    if (tid < 128) {
        int r = rowbase + tid;
        int src = 0, dst = -1; float w = 0.f;
        if (r < cnt) {
            if (FFN1) { src = g_tok[e * T_TOK + r];  dst = g_slot[e * T_TOK + r]; }
            else      { src = g_slot[e * T_TOK + r]; dst = g_slot[e * T_TOK + r];
                        w = g_wt[e * T_TOK + r]; }
        }
        src_s[tid] = src; dst_s[tid] = dst; wt_s[tid] = w;
        bias_s[tid] = Bias[(size_t)e * NTOT + nbase + tid];
    }
    __syncthreads();

    uint32_t smb = smem_u32(smdyn);

    int arow = tid >> 1;
    int acol = (tid & 1) * 16;
    const __half* aP = Ain + (size_t)src_s[arow] * KTOT + acol;
    uint32_t a_dst0 = (uint32_t)(arow * ASTR + acol) * 2;
    int brow = tid >> 3;
    int bcol = (tid & 7) * 16;
    const __half* bP = W16 + (size_t)e * KTOT * NTOT + (size_t)brow * NTOT + nbase + bcol;
    uint32_t b_dst0 = (uint32_t)(A_STAGE_B) + (uint32_t)(brow * BSTR + bcol) * 2;

    int lr = lane & 15, lc = lane >> 4;
    uint32_t a_ld0 = (uint32_t)((wm * 64 + lr) * ASTR + lc * 8) * 2;
    uint32_t b_ld0 = (uint32_t)(A_STAGE_B) + (uint32_t)(lr * BSTR + wn * 32 + lc * 8) * 2;

    float acc[4][4][4];
#pragma unroll
    for (int i = 0; i < 4; i++)
#pragma unroll
        for (int j = 0; j < 4; j++)
#pragma unroll
            for (int k = 0; k < 4; k++) acc[i][j][k] = 0.f;

#pragma unroll 1
    for (int s = 0; s < STAGES - 1; s++) {
        uint32_t sb = smb + (uint32_t)s * STAGE_B;
        int k0 = s * 32;
        const __half* ap = aP + k0;
        cp16(sb + a_dst0,      ap);
        cp16(sb + a_dst0 + 16, ap + 8);
        const __half* bp = bP + (size_t)k0 * NTOT;
        cp16(sb + b_dst0,      bp);
        cp16(sb + b_dst0 + 16, bp + 8);
        cp_commit();
    }

#pragma unroll 1
    for (int c = 0; c < NC; c++) {
        cp_wait<STAGES - 2>();
        __syncthreads();
        if (c + STAGES - 1 < NC) {
            int cs = c + STAGES - 1;
            uint32_t sbw = smb + (uint32_t)(cs % STAGES) * STAGE_B;
            int k0 = cs * 32;
            const __half* ap = aP + k0;
            cp16(sbw + a_dst0,      ap);
            cp16(sbw + a_dst0 + 16, ap + 8);
            const __half* bp = bP + (size_t)k0 * NTOT;
            cp16(sbw + b_dst0,      bp);
            cp16(sbw + b_dst0 + 16, bp + 8);
        }
        cp_commit();
        uint32_t sb = smb + (uint32_t)(c % STAGES) * STAGE_B;
#pragma unroll
        for (int ks = 0; ks < 2; ks++) {
            uint32_t afr[4][4], bfr[2][4];
#pragma unroll
            for (int mf = 0; mf < 4; mf++)
                ldsm_x4(afr[mf], sb + a_ld0 + (uint32_t)(mf * 16 * ASTR + ks * 16) * 2);
#pragma unroll
            for (int np = 0; np < 2; np++)
                ldsm_x4_t(bfr[np], sb + b_ld0 + (uint32_t)(ks * 16 * BSTR + np * 16) * 2);
#pragma unroll
            for (int mf = 0; mf < 4; mf++)
#pragma unroll
                for (int nf = 0; nf < 4; nf++)
                    mma16816(acc[mf][nf], afr[mf], &bfr[nf >> 1][(nf & 1) * 2]);
        }
    }

    // ---- epilogue ----
    int crow = lane >> 2;
    int ccol = (lane & 3) * 2;
#pragma unroll
    for (int mf = 0; mf < 4; mf++) {
#pragma unroll
        for (int half_ = 0; half_ < 2; half_++) {
            int mloc = wm * 64 + mf * 16 + crow + half_ * 8;
            int dst = dst_s[mloc];
            if (dst < 0) continue;
            float wv = wt_s[mloc];
#pragma unroll
            for (int nf = 0; nf < 4; nf++) {
                int nloc = wn * 32 + nf * 8 + ccol;
                float v0 = acc[mf][nf][half_ * 2 + 0] + bias_s[nloc];
                float v1 = acc[mf][nf][half_ * 2 + 1] + bias_s[nloc + 1];
                if (FFN1) {
                    v0 = 0.5f * v0 * (1.0f + erff(v0 * 0.70710678118654752f));
                    v1 = 0.5f * v1 * (1.0f + erff(v1 * 0.70710678118654752f));
                    __half2 h = __floats2half2_rn(v0, v1);
                    *(__half2*)(g_mid + (size_t)dst * NTOT + nbase + nloc) = h;
                } else {
                    float2 o = make_float2(wv * v0, wv * v1);
                    *(float2*)(g_out2 + (size_t)dst * NTOT + nbase + nloc) = o;
                }
            }
        }
    }
}

// ---------------------------------------------------------------------------
extern "C" void kernel_launch(void* const* d_in, const int* in_sizes, int n_in,
                              void* d_out, int out_size) {
    const float* x      = (const float*)d_in[0];
    const float* gate_w = (const float*)d_in[1];
    const float* gate_b = (const float*)d_in[2];
    const float* w1     = (const float*)d_in[3];
    const float* b1     = (const float*)d_in[4];
    const float* w2     = (const float*)d_in[5];
    const float* b2     = (const float*)d_in[6];
    float* out    = (float*)d_out;
    float* logits = (float*)d_out + OUT_ELEMS;
    (void)in_sizes; (void)n_in; (void)out_size;

    __half *px, *pw1, *pw2, *pmid;
    cudaGetSymbolAddress((void**)&px,   g_x16);
    cudaGetSymbolAddress((void**)&pw1,  g_w1h);
    cudaGetSymbolAddress((void**)&pw2,  g_w2h);
    cudaGetSymbolAddress((void**)&pmid, g_mid);

    cudaFuncSetAttribute(moe_gemm_kernel<D_DIM, H_DIM, true>,
                         cudaFuncAttributeMaxDynamicSharedMemorySize, SM_DYN);
    cudaFuncSetAttribute(moe_gemm_kernel<H_DIM, D_DIM, false>,
                         cudaFuncAttributeMaxDynamicSharedMemorySize, SM_DYN);

    zero_cnt_kernel<<<1, 32>>>();
    router_kernel<<<(T_TOK * 32) / 256, 256>>>(x, gate_w, gate_b, logits);

    int nw8 = E_NUM * D_DIM * H_DIM / 8;
    convert_kernel<<<(nw8 + 255) / 256, 256>>>((const float4*)w1, (uint4*)pw1, nw8);
    convert_kernel<<<(nw8 + 255) / 256, 256>>>((const float4*)w2, (uint4*)pw2, nw8);

    dim3 g1(T_TOK / 128, H_DIM / 128, E_NUM);   // (64, 32, 8)
    moe_gemm_kernel<D_DIM, H_DIM, true><<<g1, 256, SM_DYN>>>(px, pw1, b1);

    dim3 g2(T_TOK / 128, D_DIM / 128, E_NUM);   // (64, 8, 8)
    moe_gemm_kernel<H_DIM, D_DIM, false><<<g2, 256, SM_DYN>>>(pmid, pw2, b2);

    combine_kernel<<<(OUT_ELEMS / 4 + 255) / 256, 256>>>((float4*)out);
}

// round 13
// speedup vs baseline: 1.0391x; 1.0080x over previous
#include <cuda_runtime.h>
#include <cuda_fp16.h>
#include <math.h>
#include <stdint.h>

#define T_TOK 8192
#define D_DIM 1024
#define H_DIM 4096
#define E_NUM 8
#define OUT_ELEMS (T_TOK * D_DIM)

// ---------------- scratch ----------------
__device__ __half g_x16[(size_t)T_TOK * D_DIM];            // 16 MiB
__device__ __half g_w1h[(size_t)E_NUM * D_DIM * H_DIM];    // 64 MiB
__device__ __half g_w2h[(size_t)E_NUM * H_DIM * D_DIM];    // 64 MiB
__device__ __half g_mid[(size_t)2 * T_TOK * H_DIM];        // 128 MiB
__device__ float  g_out2[(size_t)2 * T_TOK * D_DIM];       // 64 MiB
__device__ int   g_cnt[E_NUM];
__device__ int   g_tok[E_NUM * T_TOK];
__device__ int   g_slot[E_NUM * T_TOK];
__device__ float g_wt[E_NUM * T_TOK];

__device__ __forceinline__ uint32_t smem_u32(const void* p) {
    uint32_t a;
    asm("{ .reg .u64 t; cvta.to.shared.u64 t, %1; cvt.u32.u64 %0, t; }" : "=r"(a) : "l"(p));
    return a;
}
__device__ __forceinline__ void cp16(uint32_t dst, const void* src) {
    asm volatile("cp.async.cg.shared.global [%0], [%1], 16;" :: "r"(dst), "l"(src) : "memory");
}
__device__ __forceinline__ void cp_commit() {
    asm volatile("cp.async.commit_group;" ::: "memory");
}
template<int N>
__device__ __forceinline__ void cp_wait() {
    asm volatile("cp.async.wait_group %0;" :: "n"(N) : "memory");
}
__device__ __forceinline__ void ldsm_x4(uint32_t* r, uint32_t addr) {
    asm volatile("ldmatrix.sync.aligned.m8n8.x4.shared.b16 {%0,%1,%2,%3}, [%4];"
                 : "=r"(r[0]), "=r"(r[1]), "=r"(r[2]), "=r"(r[3]) : "r"(addr));
}
__device__ __forceinline__ void ldsm_x4_t(uint32_t* r, uint32_t addr) {
    asm volatile("ldmatrix.sync.aligned.m8n8.x4.trans.shared.b16 {%0,%1,%2,%3}, [%4];"
                 : "=r"(r[0]), "=r"(r[1]), "=r"(r[2]), "=r"(r[3]) : "r"(addr));
}
__device__ __forceinline__ void mma16816(float* c, const uint32_t* a, const uint32_t* b) {
    asm volatile(
        "mma.sync.aligned.m16n8k16.row.col.f32.f16.f16.f32 "
        "{%0,%1,%2,%3}, {%4,%5,%6,%7}, {%8,%9}, {%0,%1,%2,%3};"
        : "+f"(c[0]), "+f"(c[1]), "+f"(c[2]), "+f"(c[3])
        : "r"(a[0]), "r"(a[1]), "r"(a[2]), "r"(a[3]), "r"(b[0]), "r"(b[1]));
}

// ---------------- small kernels ----------------
__global__ void zero_cnt_kernel() {
    if (threadIdx.x < E_NUM) g_cnt[threadIdx.x] = 0;
}

__global__ __launch_bounds__(256) void combine_kernel(float4* __restrict__ out) {
    int i = blockIdx.x * blockDim.x + threadIdx.x;
    if (i >= OUT_ELEMS / 4) return;
    int t = i / (D_DIM / 4);
    int r = i % (D_DIM / 4);
    const float4* a = (const float4*)g_out2 + (size_t)(2 * t) * (D_DIM / 4) + r;
    const float4* b = (const float4*)g_out2 + (size_t)(2 * t + 1) * (D_DIM / 4) + r;
    float4 va = *a, vb = *b;
    out[i] = make_float4(va.x + vb.x, va.y + vb.y, va.z + vb.z, va.w + vb.w);
}

// ---------------- fused preamble: router + x convert + both weight converts --
#define RB 1024                                   // router blocks (8 warps each)
#define NW8 (E_NUM * D_DIM * H_DIM / 8)           // 4194304 groups per weight
#define CONV_BLOCKS (2 * NW8 / 256)               // 32768
#define PRE_GRID (RB + CONV_BLOCKS)

__global__ __launch_bounds__(256) void preamble_kernel(
    const float* __restrict__ x, const float* __restrict__ gw,
    const float* __restrict__ gb, float* __restrict__ logits_out,
    const float4* __restrict__ w1f, const float4* __restrict__ w2f) {
    int b = blockIdx.x;
    if (b >= RB) {
        // ---- weight convert path (fp32 -> fp16, 8 elems/thread) ----
        int idx = (b - RB) * 256 + threadIdx.x;     // 0 .. 2*NW8-1
        const float4* src; uint4* dst; int j;
        if (idx < NW8) { j = idx;        src = w1f; dst = (uint4*)g_w1h; }
        else           { j = idx - NW8;  src = w2f; dst = (uint4*)g_w2h; }
        float4 v0 = src[2 * j], v1 = src[2 * j + 1];
        __half2 h0 = __floats2half2_rn(v0.x, v0.y);
        __half2 h1 = __floats2half2_rn(v0.z, v0.w);
        __half2 h2 = __floats2half2_rn(v1.x, v1.y);
        __half2 h3 = __floats2half2_rn(v1.z, v1.w);
        dst[j] = make_uint4(*(uint32_t*)&h0, *(uint32_t*)&h1,
                            *(uint32_t*)&h2, *(uint32_t*)&h3);
        return;
    }
    // ---- router path (R12 logic, one warp per token, fused x convert) ----
    int warp = b * 8 + (threadIdx.x >> 5);
    int lane = threadIdx.x & 31;
    int t = warp;

    float acc[E_NUM];
#pragma unroll
    for (int e = 0; e < E_NUM; e++) acc[e] = 0.f;
    const float* xr = x + (size_t)t * D_DIM;
    __half* xo = g_x16 + (size_t)t * D_DIM;
    for (int d = lane; d < D_DIM; d += 32) {
        float xv = xr[d];
        xo[d] = __float2half_rn(xv);
        const float4* g4 = (const float4*)(gw + (size_t)d * E_NUM);
        float4 a = g4[0], bb = g4[1];
        acc[0] += xv * a.x;  acc[1] += xv * a.y;  acc[2] += xv * a.z;  acc[3] += xv * a.w;
        acc[4] += xv * bb.x; acc[5] += xv * bb.y; acc[6] += xv * bb.z; acc[7] += xv * bb.w;
    }
#pragma unroll
    for (int e = 0; e < E_NUM; e++)
#pragma unroll
        for (int off = 16; off; off >>= 1)
            acc[e] += __shfl_xor_sync(0xffffffffu, acc[e], off);

    if (lane == 0) {
        float l[E_NUM];
#pragma unroll
        for (int e = 0; e < E_NUM; e++) {
            l[e] = acc[e] + gb[e];
            logits_out[t * E_NUM + e] = l[e];
        }
        float m = l[0];
#pragma unroll
        for (int e = 1; e < E_NUM; e++) m = fmaxf(m, l[e]);
        float p[E_NUM], s = 0.f;
#pragma unroll
        for (int e = 0; e < E_NUM; e++) { p[e] = expf(l[e] - m); s += p[e]; }
#pragma unroll
        for (int e = 0; e < E_NUM; e++) p[e] = p[e] / s;
        int e0 = 0;
#pragma unroll
        for (int e = 1; e < E_NUM; e++) if (p[e] > p[e0]) e0 = e;
        int e1 = (e0 == 0) ? 1 : 0;
#pragma unroll
        for (int e = 0; e < E_NUM; e++)
            if (e != e0 && p[e] > p[e1]) e1 = e;
        float denom = p[e0] + p[e1];

        int pos0 = atomicAdd(&g_cnt[e0], 1);
        g_tok[e0 * T_TOK + pos0]  = t;
        g_slot[e0 * T_TOK + pos0] = 2 * t;
        g_wt[e0 * T_TOK + pos0]   = p[e0] / denom;
        int pos1 = atomicAdd(&g_cnt[e1], 1);
        g_tok[e1 * T_TOK + pos1]  = t;
        g_slot[e1 * T_TOK + pos1] = 2 * t + 1;
        g_wt[e1 * T_TOK + pos1]   = p[e1] / denom;
    }
}

// ------- grouped GEMM: 128x128 tile, warp 64x32, cp.async 4-stage, 2 CTA/SM --
// (byte-identical to the proven 1102us R7 configuration)
#define ASTR 40      // halfs per A smem row (32 + 8 pad) = 80B
#define BSTR 136     // halfs per B smem row (128 + 8 pad) = 272B
#define A_STAGE_B (128 * ASTR * 2)          // 10240
#define B_STAGE_B (32 * BSTR * 2)           // 8704
#define STAGE_B   (A_STAGE_B + B_STAGE_B)   // 18944
#define STAGES    4
#define SM_DYN    (STAGES * STAGE_B)        // 75776

template<int KTOT, int NTOT, bool FFN1>
__global__ __launch_bounds__(256, 2) void moe_gemm_kernel(
    const __half* __restrict__ Ain, const __half* __restrict__ W16,
    const float* __restrict__ Bias)
{
    const int NC = KTOT / 32;
    int e = blockIdx.z;
    int cnt = g_cnt[e];
    int rowbase = blockIdx.x * 128;
    if (rowbase >= cnt) return;
    int nbase = blockIdx.y * 128;
    int tid = threadIdx.x;
    int lane = tid & 31;
    int warp = tid >> 5;
    int wm = warp >> 2, wn = warp & 3;    // 2 x 4 warps, warp tile 64x32

    extern __shared__ char smdyn[];
    __shared__ int   dst_s[128];
    __shared__ float wt_s[128];
    __shared__ float bias_s[128];
    __shared__ int   src_s[128];

    if (tid < 128) {
        int r = rowbase + tid;
        int src = 0, dst = -1; float w = 0.f;
        if (r < cnt) {
            if (FFN1) { src = g_tok[e * T_TOK + r];  dst = g_slot[e * T_TOK + r]; }
            else      { src = g_slot[e * T_TOK + r]; dst = g_slot[e * T_TOK + r];
                        w = g_wt[e * T_TOK + r]; }
        }
        src_s[tid] = src; dst_s[tid] = dst; wt_s[tid] = w;
        bias_s[tid] = Bias[(size_t)e * NTOT + nbase + tid];
    }
    __syncthreads();

    uint32_t smb = smem_u32(smdyn);

    int arow = tid >> 1;
    int acol = (tid & 1) * 16;
    const __half* aP = Ain + (size_t)src_s[arow] * KTOT + acol;
    uint32_t a_dst0 = (uint32_t)(arow * ASTR + acol) * 2;
    int brow = tid >> 3;
    int bcol = (tid & 7) * 16;
    const __half* bP = W16 + (size_t)e * KTOT * NTOT + (size_t)brow * NTOT + nbase + bcol;
    uint32_t b_dst0 = (uint32_t)(A_STAGE_B) + (uint32_t)(brow * BSTR + bcol) * 2;

    int lr = lane & 15, lc = lane >> 4;
    uint32_t a_ld0 = (uint32_t)((wm * 64 + lr) * ASTR + lc * 8) * 2;
    uint32_t b_ld0 = (uint32_t)(A_STAGE_B) + (uint32_t)(lr * BSTR + wn * 32 + lc * 8) * 2;

    float acc[4][4][4];
#pragma unroll
    for (int i = 0; i < 4; i++)
#pragma unroll
        for (int j = 0; j < 4; j++)
#pragma unroll
            for (int k = 0; k < 4; k++) acc[i][j][k] = 0.f;

#pragma unroll 1
    for (int s = 0; s < STAGES - 1; s++) {
        uint32_t sb = smb + (uint32_t)s * STAGE_B;
        int k0 = s * 32;
        const __half* ap = aP + k0;
        cp16(sb + a_dst0,      ap);
        cp16(sb + a_dst0 + 16, ap + 8);
        const __half* bp = bP + (size_t)k0 * NTOT;
        cp16(sb + b_dst0,      bp);
        cp16(sb + b_dst0 + 16, bp + 8);
        cp_commit();
    }

#pragma unroll 1
    for (int c = 0; c < NC; c++) {
        cp_wait<STAGES - 2>();
        __syncthreads();
        if (c + STAGES - 1 < NC) {
            int cs = c + STAGES - 1;
            uint32_t sbw = smb + (uint32_t)(cs % STAGES) * STAGE_B;
            int k0 = cs * 32;
            const __half* ap = aP + k0;
            cp16(sbw + a_dst0,      ap);
            cp16(sbw + a_dst0 + 16, ap + 8);
            const __half* bp = bP + (size_t)k0 * NTOT;
            cp16(sbw + b_dst0,      bp);
            cp16(sbw + b_dst0 + 16, bp + 8);
        }
        cp_commit();
        uint32_t sb = smb + (uint32_t)(c % STAGES) * STAGE_B;
#pragma unroll
        for (int ks = 0; ks < 2; ks++) {
            uint32_t afr[4][4], bfr[2][4];
#pragma unroll
            for (int mf = 0; mf < 4; mf++)
                ldsm_x4(afr[mf], sb + a_ld0 + (uint32_t)(mf * 16 * ASTR + ks * 16) * 2);
#pragma unroll
            for (int np = 0; np < 2; np++)
                ldsm_x4_t(bfr[np], sb + b_ld0 + (uint32_t)(ks * 16 * BSTR + np * 16) * 2);
#pragma unroll
            for (int mf = 0; mf < 4; mf++)
#pragma unroll
                for (int nf = 0; nf < 4; nf++)
                    mma16816(acc[mf][nf], afr[mf], &bfr[nf >> 1][(nf & 1) * 2]);
        }
    }

    // ---- epilogue ----
    int crow = lane >> 2;
    int ccol = (lane & 3) * 2;
#pragma unroll
    for (int mf = 0; mf < 4; mf++) {
#pragma unroll
        for (int half_ = 0; half_ < 2; half_++) {
            int mloc = wm * 64 + mf * 16 + crow + half_ * 8;
            int dst = dst_s[mloc];
            if (dst < 0) continue;
            float wv = wt_s[mloc];
#pragma unroll
            for (int nf = 0; nf < 4; nf++) {
                int nloc = wn * 32 + nf * 8 + ccol;
                float v0 = acc[mf][nf][half_ * 2 + 0] + bias_s[nloc];
                float v1 = acc[mf][nf][half_ * 2 + 1] + bias_s[nloc + 1];
                if (FFN1) {
                    v0 = 0.5f * v0 * (1.0f + erff(v0 * 0.70710678118654752f));
                    v1 = 0.5f * v1 * (1.0f + erff(v1 * 0.70710678118654752f));
                    __half2 h = __floats2half2_rn(v0, v1);
                    *(__half2*)(g_mid + (size_t)dst * NTOT + nbase + nloc) = h;
                } else {
                    float2 o = make_float2(wv * v0, wv * v1);
                    *(float2*)(g_out2 + (size_t)dst * NTOT + nbase + nloc) = o;
                }
            }
        }
    }
}

// ---------------------------------------------------------------------------
extern "C" void kernel_launch(void* const* d_in, const int* in_sizes, int n_in,
                              void* d_out, int out_size) {
    const float* x      = (const float*)d_in[0];
    const float* gate_w = (const float*)d_in[1];
    const float* gate_b = (const float*)d_in[2];
    const float* w1     = (const float*)d_in[3];
    const float* b1     = (const float*)d_in[4];
    const float* w2     = (const float*)d_in[5];
    const float* b2     = (const float*)d_in[6];
    float* out    = (float*)d_out;
    float* logits = (float*)d_out + OUT_ELEMS;
    (void)in_sizes; (void)n_in; (void)out_size;

    __half *px, *pmid, *pw1, *pw2;
    cudaGetSymbolAddress((void**)&px,   g_x16);
    cudaGetSymbolAddress((void**)&pmid, g_mid);
    cudaGetSymbolAddress((void**)&pw1,  g_w1h);
    cudaGetSymbolAddress((void**)&pw2,  g_w2h);

    cudaFuncSetAttribute(moe_gemm_kernel<D_DIM, H_DIM, true>,
                         cudaFuncAttributeMaxDynamicSharedMemorySize, SM_DYN);
    cudaFuncSetAttribute(moe_gemm_kernel<H_DIM, D_DIM, false>,
                         cudaFuncAttributeMaxDynamicSharedMemorySize, SM_DYN);

    zero_cnt_kernel<<<1, 32>>>();
    preamble_kernel<<<PRE_GRID, 256>>>(x, gate_w, gate_b, logits,
                                       (const float4*)w1, (const float4*)w2);

    dim3 g1(T_TOK / 128, H_DIM / 128, E_NUM);   // (64, 32, 8)
    moe_gemm_kernel<D_DIM, H_DIM, true><<<g1, 256, SM_DYN>>>(px, pw1, b1);

    dim3 g2(T_TOK / 128, D_DIM / 128, E_NUM);   // (64, 8, 8)
    moe_gemm_kernel<H_DIM, D_DIM, false><<<g2, 256, SM_DYN>>>(pmid, pw2, b2);

    combine_kernel<<<(OUT_ELEMS / 4 + 255) / 256, 256>>>((float4*)out);
}

// round 14
// speedup vs baseline: 1.0941x; 1.0529x over previous
#include <cuda_runtime.h>
#include <cuda_fp16.h>
#include <math.h>
#include <stdint.h>

#define T_TOK 8192
#define D_DIM 1024
#define H_DIM 4096
#define E_NUM 8
#define OUT_ELEMS (T_TOK * D_DIM)

// ---------------- scratch ----------------
__device__ __half g_x16[(size_t)T_TOK * D_DIM];            // 16 MiB
__device__ __half g_w1h[(size_t)E_NUM * D_DIM * H_DIM];    // 64 MiB
__device__ __half g_w2h[(size_t)E_NUM * H_DIM * D_DIM];    // 64 MiB
__device__ __half g_mid[(size_t)2 * T_TOK * H_DIM];        // 128 MiB
__device__ float  g_out2[(size_t)2 * T_TOK * D_DIM];       // 64 MiB
__device__ int   g_cnt[E_NUM];
__device__ int   g_tok[E_NUM * T_TOK];
__device__ int   g_slot[E_NUM * T_TOK];
__device__ float g_wt[E_NUM * T_TOK];

__device__ __forceinline__ uint32_t smem_u32(const void* p) {
    uint32_t a;
    asm("{ .reg .u64 t; cvta.to.shared.u64 t, %1; cvt.u32.u64 %0, t; }" : "=r"(a) : "l"(p));
    return a;
}
__device__ __forceinline__ void cp16(uint32_t dst, const void* src) {
    asm volatile("cp.async.cg.shared.global [%0], [%1], 16;" :: "r"(dst), "l"(src) : "memory");
}
__device__ __forceinline__ void cp_commit() {
    asm volatile("cp.async.commit_group;" ::: "memory");
}
template<int N>
__device__ __forceinline__ void cp_wait() {
    asm volatile("cp.async.wait_group %0;" :: "n"(N) : "memory");
}
__device__ __forceinline__ void ldsm_x4(uint32_t* r, uint32_t addr) {
    asm volatile("ldmatrix.sync.aligned.m8n8.x4.shared.b16 {%0,%1,%2,%3}, [%4];"
                 : "=r"(r[0]), "=r"(r[1]), "=r"(r[2]), "=r"(r[3]) : "r"(addr));
}
__device__ __forceinline__ void ldsm_x4_t(uint32_t* r, uint32_t addr) {
    asm volatile("ldmatrix.sync.aligned.m8n8.x4.trans.shared.b16 {%0,%1,%2,%3}, [%4];"
                 : "=r"(r[0]), "=r"(r[1]), "=r"(r[2]), "=r"(r[3]) : "r"(addr));
}
__device__ __forceinline__ void mma16816(float* c, const uint32_t* a, const uint32_t* b) {
    asm volatile(
        "mma.sync.aligned.m16n8k16.row.col.f32.f16.f16.f32 "
        "{%0,%1,%2,%3}, {%4,%5,%6,%7}, {%8,%9}, {%0,%1,%2,%3};"
        : "+f"(c[0]), "+f"(c[1]), "+f"(c[2]), "+f"(c[3])
        : "r"(a[0]), "r"(a[1]), "r"(a[2]), "r"(a[3]), "r"(b[0]), "r"(b[1]));
}

// ---------------- small kernels ----------------
__global__ void zero_cnt_kernel() {
    if (threadIdx.x < E_NUM) g_cnt[threadIdx.x] = 0;
}

__global__ __launch_bounds__(256) void combine_kernel(float4* __restrict__ out) {
    int i = blockIdx.x * blockDim.x + threadIdx.x;
    if (i >= OUT_ELEMS / 4) return;
    int t = i / (D_DIM / 4);
    int r = i % (D_DIM / 4);
    const float4* a = (const float4*)g_out2 + (size_t)(2 * t) * (D_DIM / 4) + r;
    const float4* b = (const float4*)g_out2 + (size_t)(2 * t + 1) * (D_DIM / 4) + r;
    float4 va = *a, vb = *b;
    out[i] = make_float4(va.x + vb.x, va.y + vb.y, va.z + vb.z, va.w + vb.w);
}

// ---------------- fused preamble: router + x convert + both weight converts --
#define RB 1024
#define NW8 (E_NUM * D_DIM * H_DIM / 8)
#define CONV_BLOCKS (2 * NW8 / 256)
#define PRE_GRID (RB + CONV_BLOCKS)

__global__ __launch_bounds__(256) void preamble_kernel(
    const float* __restrict__ x, const float* __restrict__ gw,
    const float* __restrict__ gb, float* __restrict__ logits_out,
    const float4* __restrict__ w1f, const float4* __restrict__ w2f) {
    int b = blockIdx.x;
    if (b >= RB) {
        int idx = (b - RB) * 256 + threadIdx.x;
        const float4* src; uint4* dst; int j;
        if (idx < NW8) { j = idx;        src = w1f; dst = (uint4*)g_w1h; }
        else           { j = idx - NW8;  src = w2f; dst = (uint4*)g_w2h; }
        float4 v0 = src[2 * j], v1 = src[2 * j + 1];
        __half2 h0 = __floats2half2_rn(v0.x, v0.y);
        __half2 h1 = __floats2half2_rn(v0.z, v0.w);
        __half2 h2 = __floats2half2_rn(v1.x, v1.y);
        __half2 h3 = __floats2half2_rn(v1.z, v1.w);
        dst[j] = make_uint4(*(uint32_t*)&h0, *(uint32_t*)&h1,
                            *(uint32_t*)&h2, *(uint32_t*)&h3);
        return;
    }
    int warp = b * 8 + (threadIdx.x >> 5);
    int lane = threadIdx.x & 31;
    int t = warp;

    float acc[E_NUM];
#pragma unroll
    for (int e = 0; e < E_NUM; e++) acc[e] = 0.f;
    const float* xr = x + (size_t)t * D_DIM;
    __half* xo = g_x16 + (size_t)t * D_DIM;
    for (int d = lane; d < D_DIM; d += 32) {
        float xv = xr[d];
        xo[d] = __float2half_rn(xv);
        const float4* g4 = (const float4*)(gw + (size_t)d * E_NUM);
        float4 a = g4[0], bb = g4[1];
        acc[0] += xv * a.x;  acc[1] += xv * a.y;  acc[2] += xv * a.z;  acc[3] += xv * a.w;
        acc[4] += xv * bb.x; acc[5] += xv * bb.y; acc[6] += xv * bb.z; acc[7] += xv * bb.w;
    }
#pragma unroll
    for (int e = 0; e < E_NUM; e++)
#pragma unroll
        for (int off = 16; off; off >>= 1)
            acc[e] += __shfl_xor_sync(0xffffffffu, acc[e], off);

    if (lane == 0) {
        float l[E_NUM];
#pragma unroll
        for (int e = 0; e < E_NUM; e++) {
            l[e] = acc[e] + gb[e];
            logits_out[t * E_NUM + e] = l[e];
        }
        float m = l[0];
#pragma unroll
        for (int e = 1; e < E_NUM; e++) m = fmaxf(m, l[e]);
        float p[E_NUM], s = 0.f;
#pragma unroll
        for (int e = 0; e < E_NUM; e++) { p[e] = expf(l[e] - m); s += p[e]; }
#pragma unroll
        for (int e = 0; e < E_NUM; e++) p[e] = p[e] / s;
        int e0 = 0;
#pragma unroll
        for (int e = 1; e < E_NUM; e++) if (p[e] > p[e0]) e0 = e;
        int e1 = (e0 == 0) ? 1 : 0;
#pragma unroll
        for (int e = 0; e < E_NUM; e++)
            if (e != e0 && p[e] > p[e1]) e1 = e;
        float denom = p[e0] + p[e1];

        int pos0 = atomicAdd(&g_cnt[e0], 1);
        g_tok[e0 * T_TOK + pos0]  = t;
        g_slot[e0 * T_TOK + pos0] = 2 * t;
        g_wt[e0 * T_TOK + pos0]   = p[e0] / denom;
        int pos1 = atomicAdd(&g_cnt[e1], 1);
        g_tok[e1 * T_TOK + pos1]  = t;
        g_slot[e1 * T_TOK + pos1] = 2 * t + 1;
        g_wt[e1 * T_TOK + pos1]   = p[e1] / denom;
    }
}

// -- grouped GEMM: 128x128 tile, warp 64x32, 5-buffer ring, 2 chunks/iter ----
#define ASTR 40      // halfs per A smem row (32 + 8 pad) = 80B
#define BSTR 136     // halfs per B smem row (128 + 8 pad) = 272B
#define A_STAGE_B (128 * ASTR * 2)          // 10240
#define B_STAGE_B (32 * BSTR * 2)           // 8704
#define STAGE_B   (A_STAGE_B + B_STAGE_B)   // 18944
#define RING      5
#define SM_DYN    (RING * STAGE_B)          // 94720

template<int KTOT, int NTOT, bool FFN1>
__global__ __launch_bounds__(256, 2) void moe_gemm_kernel(
    const __half* __restrict__ Ain, const __half* __restrict__ W16,
    const float* __restrict__ Bias)
{
    const int NC = KTOT / 32;                // even for both GEMMs
    int e = blockIdx.z;
    int cnt = g_cnt[e];
    int rowbase = blockIdx.x * 128;
    if (rowbase >= cnt) return;
    int nbase = blockIdx.y * 128;
    int tid = threadIdx.x;
    int lane = tid & 31;
    int warp = tid >> 5;
    int wm = warp >> 2, wn = warp & 3;       // 2 x 4 warps, warp tile 64x32

    extern __shared__ char smdyn[];
    __shared__ int   dst_s[128];
    __shared__ float wt_s[128];
    __shared__ float bias_s[128];
    __shared__ int   src_s[128];

    if (tid < 128) {
        int r = rowbase + tid;
        int src = 0, dst = -1; float w = 0.f;
        if (r < cnt) {
            if (FFN1) { src = g_tok[e * T_TOK + r];  dst = g_slot[e * T_TOK + r]; }
            else      { src = g_slot[e * T_TOK + r]; dst = g_slot[e * T_TOK + r];
                        w = g_wt[e * T_TOK + r]; }
        }
        src_s[tid] = src; dst_s[tid] = dst; wt_s[tid] = w;
        bias_s[tid] = Bias[(size_t)e * NTOT + nbase + tid];
    }
    __syncthreads();

    uint32_t smb = smem_u32(smdyn);

    int arow = tid >> 1;
    int acol = (tid & 1) * 16;
    const __half* aP = Ain + (size_t)src_s[arow] * KTOT + acol;
    uint32_t a_dst0 = (uint32_t)(arow * ASTR + acol) * 2;
    int brow = tid >> 3;
    int bcol = (tid & 7) * 16;
    const __half* bP = W16 + (size_t)e * KTOT * NTOT + (size_t)brow * NTOT + nbase + bcol;
    uint32_t b_dst0 = (uint32_t)(A_STAGE_B) + (uint32_t)(brow * BSTR + bcol) * 2;

    int lr = lane & 15, lc = lane >> 4;
    uint32_t a_ld0 = (uint32_t)((wm * 64 + lr) * ASTR + lc * 8) * 2;
    uint32_t b_ld0 = (uint32_t)(A_STAGE_B) + (uint32_t)(lr * BSTR + wn * 32 + lc * 8) * 2;

    float acc[4][4][4];
#pragma unroll
    for (int i = 0; i < 4; i++)
#pragma unroll
        for (int j = 0; j < 4; j++)
#pragma unroll
            for (int k = 0; k < 4; k++) acc[i][j][k] = 0.f;

    // issue one chunk into ring slot (ch % RING), own commit group
    auto issue_chunk = [&](int ch) {
        uint32_t sb = smb + (uint32_t)(ch % RING) * STAGE_B;
        int k0 = ch * 32;
        const __half* ap = aP + k0;
        cp16(sb + a_dst0,      ap);
        cp16(sb + a_dst0 + 16, ap + 8);
        const __half* bp = bP + (size_t)k0 * NTOT;
        cp16(sb + b_dst0,      bp);
        cp16(sb + b_dst0 + 16, bp + 8);
        cp_commit();
    };

    // prologue: chunks 0, 1, 2 (3 commit groups)
    issue_chunk(0);
    issue_chunk(1);
    issue_chunk(2);

#pragma unroll 1
    for (int c = 0; c < NC; c += 2) {
        cp_wait<1>();          // chunks c, c+1 resident (c+2 may be pending)
        __syncthreads();       // buffers (c+3)%RING, (c+4)%RING are free
        if (c + 3 < NC) issue_chunk(c + 3); else cp_commit();
        if (c + 4 < NC) issue_chunk(c + 4); else cp_commit();
        // ---- compute chunks c and c+1 (barrier-free straightline) ----
#pragma unroll
        for (int cc = 0; cc < 2; cc++) {
            uint32_t sb = smb + (uint32_t)((c + cc) % RING) * STAGE_B;
#pragma unroll
            for (int ks = 0; ks < 2; ks++) {
                uint32_t afr[4][4], bfr[2][4];
#pragma unroll
                for (int mf = 0; mf < 4; mf++)
                    ldsm_x4(afr[mf], sb + a_ld0 + (uint32_t)(mf * 16 * ASTR + ks * 16) * 2);
#pragma unroll
                for (int np = 0; np < 2; np++)
                    ldsm_x4_t(bfr[np], sb + b_ld0 + (uint32_t)(ks * 16 * BSTR + np * 16) * 2);
#pragma unroll
                for (int mf = 0; mf < 4; mf++)
#pragma unroll
                    for (int nf = 0; nf < 4; nf++)
                        mma16816(acc[mf][nf], afr[mf], &bfr[nf >> 1][(nf & 1) * 2]);
            }
        }
    }

    // ---- epilogue ----
    int crow = lane >> 2;
    int ccol = (lane & 3) * 2;
#pragma unroll
    for (int mf = 0; mf < 4; mf++) {
#pragma unroll
        for (int half_ = 0; half_ < 2; half_++) {
            int mloc = wm * 64 + mf * 16 + crow + half_ * 8;
            int dst = dst_s[mloc];
            if (dst < 0) continue;
            float wv = wt_s[mloc];
#pragma unroll
            for (int nf = 0; nf < 4; nf++) {
                int nloc = wn * 32 + nf * 8 + ccol;
                float v0 = acc[mf][nf][half_ * 2 + 0] + bias_s[nloc];
                float v1 = acc[mf][nf][half_ * 2 + 1] + bias_s[nloc + 1];
                if (FFN1) {
                    v0 = 0.5f * v0 * (1.0f + erff(v0 * 0.70710678118654752f));
                    v1 = 0.5f * v1 * (1.0f + erff(v1 * 0.70710678118654752f));
                    __half2 h = __floats2half2_rn(v0, v1);
                    *(__half2*)(g_mid + (size_t)dst * NTOT + nbase + nloc) = h;
                } else {
                    float2 o = make_float2(wv * v0, wv * v1);
                    *(float2*)(g_out2 + (size_t)dst * NTOT + nbase + nloc) = o;
                }
            }
        }
    }
}

// ---------------------------------------------------------------------------
extern "C" void kernel_launch(void* const* d_in, const int* in_sizes, int n_in,
                              void* d_out, int out_size) {
    const float* x      = (const float*)d_in[0];
    const float* gate_w = (const float*)d_in[1];
    const float* gate_b = (const float*)d_in[2];
    const float* w1     = (const float*)d_in[3];
    const float* b1     = (const float*)d_in[4];
    const float* w2     = (const float*)d_in[5];
    const float* b2     = (const float*)d_in[6];
    float* out    = (float*)d_out;
    float* logits = (float*)d_out + OUT_ELEMS;
    (void)in_sizes; (void)n_in; (void)out_size;

    __half *px, *pmid, *pw1, *pw2;
    cudaGetSymbolAddress((void**)&px,   g_x16);
    cudaGetSymbolAddress((void**)&pmid, g_mid);
    cudaGetSymbolAddress((void**)&pw1,  g_w1h);
    cudaGetSymbolAddress((void**)&pw2,  g_w2h);

    cudaFuncSetAttribute(moe_gemm_kernel<D_DIM, H_DIM, true>,
                         cudaFuncAttributeMaxDynamicSharedMemorySize, SM_DYN);
    cudaFuncSetAttribute(moe_gemm_kernel<H_DIM, D_DIM, false>,
                         cudaFuncAttributeMaxDynamicSharedMemorySize, SM_DYN);

    zero_cnt_kernel<<<1, 32>>>();
    preamble_kernel<<<PRE_GRID, 256>>>(x, gate_w, gate_b, logits,
                                       (const float4*)w1, (const float4*)w2);

    dim3 g1(T_TOK / 128, H_DIM / 128, E_NUM);   // (64, 32, 8)
    moe_gemm_kernel<D_DIM, H_DIM, true><<<g1, 256, SM_DYN>>>(px, pw1, b1);

    dim3 g2(T_TOK / 128, D_DIM / 128, E_NUM);   // (64, 8, 8)
    moe_gemm_kernel<H_DIM, D_DIM, false><<<g2, 256, SM_DYN>>>(pmid, pw2, b2);

    combine_kernel<<<(OUT_ELEMS / 4 + 255) / 256, 256>>>((float4*)out);
}